// round 14
// baseline (speedup 1.0000x reference)
#include <cuda_runtime.h>
#include <cuda_bf16.h>
#include <stdint.h>

#define D_MODEL 4096
#define SHARDS  8
#define N_VOCAB 50400

// Allocation-free scratch.
__device__ float g_bias_sum[D_MODEL];

// Prologue (PDL primary): reduce bias over shards only.
__global__ void prologue_kernel(const float* __restrict__ b) {
    int d = blockIdx.x * blockDim.x + threadIdx.x;
    if (d < D_MODEL) {
        float s = 0.f;
#pragma unroll
        for (int k = 0; k < SHARDS; k++) s += b[k * D_MODEL + d];
        g_bias_sum[d] = s;
    }
}

// PDL secondary. ONE token row per CTA (grid=T): regs ~32 -> 8 CTAs/SM,
// ~80% occupancy. 256 threads x 4 float4 = 4096 floats per row.
// Token dtype detected locally so all W loads are independent of the
// prologue; only the bias read sits behind the grid-dependency sync.
__global__ __launch_bounds__(256) void embed_gather_kernel(
    const void* __restrict__ tok,        // [T] int32 or int64 ids
    const float* __restrict__ W,         // [N_VOCAB, D_MODEL]
    float* __restrict__ out)             // [T, D_MODEL]
{
    const int t = blockIdx.x;
    const int tid = threadIdx.x;

    // Local dtype detection: for int64 ids (< 50400 << 2^31) every odd 32-bit
    // word of the buffer is 0; for int32 ids the odd words are random tokens
    // (all-zero probability ~ (1/50400)^4). Two 16B loads, L2-resident.
    const int4* tq = (const int4*)tok;
    int4 q0 = tq[0], q1 = tq[1];
    const bool is64 = ((q0.y | q0.w | q1.y | q1.w) == 0);

    long long id = is64 ? ((const long long*)tok)[t]
                        : (long long)((const int*)tok)[t];
    // Clamp defensively: OOB would hard-fault; wrong-but-inbounds fails
    // rel_err instead, which is diagnosable.
    if (id < 0) id = 0;
    if (id >= N_VOCAB) id = N_VOCAB - 1;

    const float4* __restrict__ wrow = reinterpret_cast<const float4*>(W + (size_t)id * D_MODEL);

    // Issue all 4 W loads up front — independent of the prologue.
    float4 a[4];
#pragma unroll
    for (int i = 0; i < 4; i++) a[i] = __ldcs(&wrow[tid + i * 256]);

    // Gate only the prologue-dependent bias read. The tiny prologue finishes
    // well inside the W-load shadow, so this wait is ~free.
    cudaGridDependencySynchronize();

    const float4* __restrict__ bias = reinterpret_cast<const float4*>(g_bias_sum);
    float4* __restrict__ orow = reinterpret_cast<float4*>(out + (size_t)t * D_MODEL);

#pragma unroll
    for (int i = 0; i < 4; i++) {
        float4 bv = __ldg(&bias[tid + i * 256]);
        float4 r = a[i];
        r.x += bv.x; r.y += bv.y; r.z += bv.z; r.w += bv.w;
        __stcs(&orow[tid + i * 256], r);
    }
}

extern "C" void kernel_launch(void* const* d_in, const int* in_sizes, int n_in,
                              void* d_out, int out_size) {
    // Identify inputs by element count, independent of metadata order.
    const void* tok = nullptr;
    const float* W = nullptr;
    const float* b = nullptr;
    for (int i = 0; i < n_in; i++) {
        long long sz = in_sizes[i];
        if (sz > 100000000LL)            W   = (const float*)d_in[i];  // 50400*4096
        else if (sz == SHARDS * D_MODEL) b   = (const float*)d_in[i];  // 32768
        else                             tok = d_in[i];                // token ids
    }

    float* out = (float*)d_out;               // [T, D_MODEL]
    const int T = out_size / D_MODEL;         // 4096

    // Primary.
    prologue_kernel<<<(D_MODEL + 255) / 256, 256>>>(b);

    // Secondary with programmatic stream serialization: its CTAs launch and run
    // their W-load phase while the prologue is still in flight.
    cudaLaunchConfig_t cfg = {};
    cfg.gridDim  = dim3((unsigned)T);
    cfg.blockDim = dim3(256);
    cfg.dynamicSmemBytes = 0;
    cfg.stream = 0;  // legacy default stream (same as <<<>>>)
    cudaLaunchAttribute attr[1];
    attr[0].id = cudaLaunchAttributeProgrammaticStreamSerialization;
    attr[0].val.programmaticStreamSerializationAllowed = 1;
    cfg.attrs = attr;
    cfg.numAttrs = 1;
    cudaLaunchKernelEx(&cfg, embed_gather_kernel, tok, W, out);
}